// round 15
// baseline (speedup 1.0000x reference)
#include <cuda_runtime.h>
#include <math.h>
#include <stdint.h>

#define NN 8192
#define DD 64
#define CC 100
#define TT 30
#define HC 50
#define NPAIR 465
#define NXT (NN / 128)          // 64 x-tiles
#define NITEM (NXT * HC)        // 3200 work items
#define NBLK 592                // 148 SMs x 4 resident blocks

// ---- device-global scratch ----
__device__ float g_lp[NN * CC];
__device__ float g_G[CC * TT * 32];
__device__ float g_al[CC * 32];
__device__ float g_be[CC * 32];
__device__ float g_n0[CC * 32];

typedef unsigned long long u64;

__device__ __forceinline__ float2 upk2(u64 v) {
    float2 f; asm("mov.b64 {%0, %1}, %2;" : "=f"(f.x), "=f"(f.y) : "l"(v)); return f;
}
__device__ __forceinline__ u64 pk2(float lo, float hi) {
    u64 r; asm("mov.b64 %0, {%1, %2};" : "=l"(r) : "f"(lo), "f"(hi)); return r;
}
__device__ __forceinline__ u64 fma2(u64 a, u64 b, u64 c) {
    u64 d; asm("fma.rn.f32x2 %0, %1, %2, %3;" : "=l"(d) : "l"(a), "l"(b), "l"(c)); return d;
}
__device__ __forceinline__ u64 add2(u64 a, u64 b) {
    u64 d; asm("add.rn.f32x2 %0, %1, %2;" : "=l"(d) : "l"(a), "l"(b)); return d;
}
__device__ __forceinline__ int goff(int t) { return (t * (t - 1)) / 2 + (t >> 1); }

// ---- prep: per-class params + Gram (proven) ----
__global__ void __launch_bounds__(512) prep_kernel(const float* __restrict__ z0,
                                                   const float* __restrict__ ap,
                                                   const float* __restrict__ bp) {
    __shared__ float sz[TT * 65];
    const int tid = threadIdx.x;
    const int c = blockIdx.x;

    for (int i = tid; i < TT * DD; i += 512) {
        int r = i >> 6, col = i & 63;
        sz[r * 65 + col] = z0[(size_t)c * TT * DD + i];
    }
    if (tid < TT) {
        float a  = log1pf(__expf(ap[c * TT + tid]));
        float be = log1pf(__expf(bp[c * TT + tid])) - a;
        g_al[c * 32 + tid] = a;
        g_be[c * 32 + tid] = be;
    }
    __syncthreads();

    int k = tid;
    if (k < NPAIR) {
        int t = (int)((__fsqrt_rn(8.f * k + 1.f) - 1.f) * 0.5f);
        while ((t + 1) * (t + 2) / 2 <= k) ++t;
        while (t * (t + 1) / 2 > k) --t;
        int i = k - t * (t + 1) / 2;
        const float* za = sz + t * 65;
        const float* zb = sz + i * 65;
        float a0 = 0.f, a1 = 0.f, a2 = 0.f, a3 = 0.f;
        #pragma unroll
        for (int d = 0; d < DD; d += 4) {
            a0 = fmaf(za[d],     zb[d],     a0);
            a1 = fmaf(za[d + 1], zb[d + 1], a1);
            a2 = fmaf(za[d + 2], zb[d + 2], a2);
            a3 = fmaf(za[d + 3], zb[d + 3], a3);
        }
        float dot = (a0 + a1) + (a2 + a3);
        if (i == t) g_n0[c * 32 + t] = dot;
        else        g_G[(size_t)c * TT * 32 + t * 32 + i] = dot;
    }
}

__device__ __forceinline__ void mma_tf32(float& c0, float& c1, float& c2, float& c3,
                                         uint32_t a0, uint32_t a1, uint32_t a2, uint32_t a3,
                                         uint32_t b0, uint32_t b1) {
    asm volatile(
        "mma.sync.aligned.m16n8k8.row.col.f32.tf32.tf32.f32 "
        "{%0,%1,%2,%3}, {%4,%5,%6,%7}, {%8,%9}, {%0,%1,%2,%3};"
        : "+f"(c0), "+f"(c1), "+f"(c2), "+f"(c3)
        : "r"(a0), "r"(a1), "r"(a2), "r"(a3), "r"(b0), "r"(b1));
}

// dynamic smem (float indices):
//  sx  [0, 8704)        x tile 128 x 68; aliased by spq (u64 128 x 33)
//  szz [8704, 13056)    two z0 tiles (32 x 68 each)
//  sGc [13056, 13956)   compact paired Gram (u64[450])
//  prm [13956, 14148)
#define OFF_Z   8704
#define OFF_GC  13056
#define OFF_PRM 13956
#define SMEM_FLOATS 14148
#define SMEM_BYTES (SMEM_FLOATS * 4)   // 56592 B -> 4 blocks/SM

// ---- flow: persistent blocks, each loops over (x-tile, class-pair) items ----
__global__ void __launch_bounds__(128, 4) flow_kernel(const float* __restrict__ x,
                                                      const float* __restrict__ z0g) {
    extern __shared__ __align__(16) float sm[];
    float* sx   = sm;
    float* szz  = sm + OFF_Z;
    u64*   sGc  = (u64*)(sm + OFF_GC);
    float* prmA = sm + OFF_PRM;
    float* prmB = sm + OFF_PRM + 96;

    const int tid = threadIdx.x;
    const int wid = tid >> 5;
    const int lane = tid & 31;
    const int g = lane >> 2;
    const int cc4 = lane & 3;

    #pragma unroll 1
    for (int item = blockIdx.x; item < NITEM; item += NBLK) {
        const int xt = item / HC;
        const int pair = item - xt * HC;
        const int c0 = pair;
        const int c1 = pair + HC;
        const int nbase = xt * 128;

        __syncthreads();   // protect smem reuse across items

        // stage x tile (pitch 17 float4)
        {
            const float4* gx = (const float4*)(x + (size_t)nbase * DD);
            float4* s4 = (float4*)sx;
            #pragma unroll
            for (int j = 0; j < 16; ++j) {
                int idx = tid + 128 * j;
                int r = idx >> 4, col = idx & 15;
                s4[r * 17 + col] = gx[idx];
            }
        }
        // stage both z0 tiles (32 x 68, rows 30/31 zero)
        {
            const float* gz0 = z0g + (size_t)c0 * TT * DD;
            const float* gz1 = z0g + (size_t)c1 * TT * DD;
            #pragma unroll
            for (int i = tid; i < 4096; i += 128) {
                int cls = i >> 11;
                int ii = i & 2047;
                int r = ii >> 6, col = ii & 63;
                const float* gz = cls ? gz1 : gz0;
                szz[cls * 2176 + r * 68 + col] = (ii < 1920) ? gz[ii] : 0.f;
            }
        }
        // compact paired Gram from prep output
        {
            const float* GA = g_G + (size_t)c0 * TT * 32;
            const float* GB = g_G + (size_t)c1 * TT * 32;
            for (int k = tid; k < 450; k += 128) {
                int t = (int)__fsqrt_rn(2.f * k);
                if (t < 1) t = 1;
                if (t > 29) t = 29;
                while (t < 29 && goff(t + 1) <= k) ++t;
                while (goff(t) > k) --t;
                int i = k - goff(t);
                float a = (i < t) ? GA[t * 32 + i] : 0.f;
                float b = (i < t) ? GB[t * 32 + i] : 0.f;
                sGc[k] = pk2(a, b);
            }
        }
        // params
        if (tid < 64) {
            int cls = tid >> 5, t = tid & 31;
            int c = cls ? c1 : c0;
            float* p = cls ? prmB : prmA;
            p[t]      = g_al[c * 32 + t];
            p[32 + t] = g_be[c * 32 + t];
            p[64 + t] = g_n0[c * 32 + t];
        }
        __syncthreads();

        // q0 = ||x||^2 (own row)
        float q0;
        {
            const float4* xr = ((const float4*)sx) + tid * 17;
            float a0 = 0.f, a1 = 0.f, a2 = 0.f, a3 = 0.f;
            #pragma unroll
            for (int j = 0; j < 16; ++j) {
                float4 v = xr[j];
                a0 = fmaf(v.x, v.x, a0);
                a1 = fmaf(v.y, v.y, a1);
                a2 = fmaf(v.z, v.z, a2);
                a3 = fmaf(v.w, v.w, a3);
            }
            q0 = (a0 + a1) + (a2 + a3);
        }

        // ---- MMA: P[32 samples x 32 ts] per warp, both classes ----
        float CA[2][4][4], CB[2][4][4];
        #pragma unroll
        for (int mt = 0; mt < 2; ++mt)
            #pragma unroll
            for (int nt = 0; nt < 4; ++nt)
                #pragma unroll
                for (int r = 0; r < 4; ++r) { CA[mt][nt][r] = 0.f; CB[mt][nt][r] = 0.f; }

        const uint32_t* xa  = (const uint32_t*)(sx + (32 * wid + g) * 68);
        const uint32_t* zbA = (const uint32_t*)(szz + g * 68);
        const uint32_t* zbB = (const uint32_t*)(szz + 2176 + g * 68);

        #pragma unroll
        for (int ks = 0; ks < 8; ++ks) {
            int k0 = 8 * ks + cc4;
            uint32_t a00 = xa[k0],               a01 = xa[8 * 68 + k0];
            uint32_t a02 = xa[k0 + 4],           a03 = xa[8 * 68 + k0 + 4];
            uint32_t a10 = xa[16 * 68 + k0],     a11 = xa[24 * 68 + k0];
            uint32_t a12 = xa[16 * 68 + k0 + 4], a13 = xa[24 * 68 + k0 + 4];
            #pragma unroll
            for (int nt = 0; nt < 4; ++nt) {
                uint32_t bA0 = zbA[nt * 8 * 68 + k0];
                uint32_t bA1 = zbA[nt * 8 * 68 + k0 + 4];
                mma_tf32(CA[0][nt][0], CA[0][nt][1], CA[0][nt][2], CA[0][nt][3],
                         a00, a01, a02, a03, bA0, bA1);
                mma_tf32(CA[1][nt][0], CA[1][nt][1], CA[1][nt][2], CA[1][nt][3],
                         a10, a11, a12, a13, bA0, bA1);
                uint32_t bB0 = zbB[nt * 8 * 68 + k0];
                uint32_t bB1 = zbB[nt * 8 * 68 + k0 + 4];
                mma_tf32(CB[0][nt][0], CB[0][nt][1], CB[0][nt][2], CB[0][nt][3],
                         a00, a01, a02, a03, bB0, bB1);
                mma_tf32(CB[1][nt][0], CB[1][nt][1], CB[1][nt][2], CB[1][nt][3],
                         a10, a11, a12, a13, bB0, bB1);
            }
        }
        __syncthreads();   // x tile reads done -> alias sp

        // write paired P: spq[s*33 + t] = {pA, pB}
        u64* spq = (u64*)sx;
        #pragma unroll
        for (int mt = 0; mt < 2; ++mt) {
            #pragma unroll
            for (int nt = 0; nt < 4; ++nt) {
                int s0 = 32 * wid + mt * 16 + g;
                int t0 = nt * 8 + 2 * cc4;
                spq[s0 * 33 + t0]           = pk2(CA[mt][nt][0], CB[mt][nt][0]);
                spq[s0 * 33 + t0 + 1]       = pk2(CA[mt][nt][1], CB[mt][nt][1]);
                spq[(s0 + 8) * 33 + t0]     = pk2(CA[mt][nt][2], CB[mt][nt][2]);
                spq[(s0 + 8) * 33 + t0 + 1] = pk2(CA[mt][nt][3], CB[mt][nt][3]);
            }
        }
        __syncwarp();

        // ---- packed dual-class chain (compact Gram rows) ----
        u64 wp[TT];
        float qA = q0, qB = q0;
        float gA = 1.f, gB = 1.f, giA = 1.f, giB = 1.f, prodA = 1.f, prodB = 1.f;

        #pragma unroll
        for (int t = 0; t < TT; ++t) {
            const u64* G2 = sGc + goff(t);
            u64 acc0 = 0ull, acc1 = 0ull;
            int i = 0;
            #pragma unroll
            for (; i + 2 <= t; i += 2) {
                ulonglong2 gq = *(const ulonglong2*)(G2 + i);
                acc0 = fma2(wp[i],     gq.x, acc0);
                acc1 = fma2(wp[i + 1], gq.y, acc1);
            }
            if (i < t) acc0 = fma2(wp[i], G2[i], acc0);
            float2 dot = upk2(add2(add2(acc0, acc1), spq[tid * 33 + t]));

            float sA = gA * dot.x;
            float sB = gB * dot.y;

            float alA = prmA[t], beA = prmA[32 + t], nnA = prmA[64 + t];
            float alB = prmB[t], beB = prmB[32 + t], nnB = prmB[64 + t];

            float r2A = fmaxf(fmaf(-2.f, sA, qA) + nnA, 1e-20f);
            float r2B = fmaxf(fmaf(-2.f, sB, qB) + nnB, 1e-20f);
            float rinA = rsqrtf(r2A), rinB = rsqrtf(r2B);
            float rA = r2A * rinA,    rB = r2B * rinB;
            float dA = alA + rA,      dB = alB + rB;
            float hA = __frcp_rn(dA),        hB = __frcp_rn(dB);
            float vA = __frcp_rn(dA + beA),  vB = __frcp_rn(dB + beB);
            float bhA = beA * hA,     bhB = beB * hB;
            float opA = 1.f + bhA,    opB = 1.f + bhB;
            float t2A = opA - bhA * (hA * rA);
            float t2B = opB - bhB * (hB * rB);
            prodA *= t2A;             prodB *= t2B;
            qA = fmaf(bhA * bhA, r2A, fmaf(2.f * bhA, qA - sA, qA));
            qB = fmaf(bhB * bhB, r2B, fmaf(2.f * bhB, qB - sB, qB));
            gA *= opA;                gB *= opB;
            giA *= dA * vA;           giB *= dB * vB;
            wp[t] = pk2(-bhA * giA, -bhB * giB);
        }

        float lpA = 63.f * __logf(gA) + __logf(prodA) - 0.5f * qA - 58.8120661251f;
        float lpB = 63.f * __logf(gB) + __logf(prodB) - 0.5f * qB - 58.8120661251f;
        g_lp[(size_t)(nbase + tid) * CC + c0] = lpA;
        g_lp[(size_t)(nbase + tid) * CC + c1] = lpB;
    }
}

// ---- epilogue: warp = sample; 32 samples/block, chunked dot (proven) ----
__global__ void __launch_bounds__(1024, 1) out_kernel(const float* __restrict__ x,
                                                      const int* __restrict__ labels,
                                                      const float* __restrict__ freq,
                                                      const float* __restrict__ W,
                                                      const float* __restrict__ b,
                                                      float* __restrict__ out) {
    __shared__ __align__(16) float sWt[CC * 68];
    __shared__ __align__(16) float sxr[32 * 68];
    __shared__ float sb[CC], slf[CC];
    const int tid = threadIdx.x;
    for (int i = tid; i < DD * CC; i += 1024) {
        int d = i / CC, cc = i % CC;
        sWt[cc * 68 + d] = W[i];
    }
    for (int i = tid; i < CC; i += 1024) { sb[i] = b[i]; slf[i] = __logf(freq[i]); }

    const int wid = tid >> 5, lane = tid & 31;
    const int n = blockIdx.x * 32 + wid;
    {
        const float2* xp = (const float2*)(x + (size_t)n * DD);
        ((float2*)(sxr + wid * 68))[lane] = xp[lane];
    }
    __syncthreads();

    float lg[4] = {0.f, 0.f, 0.f, 0.f};
    const u64* xq = (const u64*)(sxr + wid * 68);
    #pragma unroll
    for (int ch = 0; ch < 4; ++ch) {
        u64 xv8[8];
        #pragma unroll
        for (int j = 0; j < 8; ++j) xv8[j] = xq[ch * 8 + j];
        #pragma unroll
        for (int k = 0; k < 4; ++k) {
            int cc = lane + 32 * k;
            if (cc < CC) {
                const ulonglong2* wr = (const ulonglong2*)(sWt + cc * 68 + ch * 16);
                u64 a0 = 0ull, a1 = 0ull;
                #pragma unroll
                for (int j = 0; j < 4; ++j) {
                    ulonglong2 v = wr[j];
                    a0 = fma2(xv8[2 * j],     v.x, a0);
                    a1 = fma2(xv8[2 * j + 1], v.y, a1);
                }
                float2 f = upk2(add2(a0, a1));
                lg[k] += f.x + f.y;
            }
        }
    }

    const float* lprow = g_lp + (size_t)n * CC;
    float lq[4];
    float mlg = -1e30f, mlp = -1e30f;
    #pragma unroll
    for (int k = 0; k < 4; ++k) {
        int cc = lane + 32 * k;
        if (cc < CC) {
            lg[k] += sb[cc];
            lq[k] = lprow[cc] + slf[cc];
        } else {
            lg[k] = -1e30f; lq[k] = -1e30f;
        }
        mlg = fmaxf(mlg, lg[k]);
        mlp = fmaxf(mlp, lq[k]);
    }
    #pragma unroll
    for (int o = 16; o; o >>= 1) {
        mlg = fmaxf(mlg, __shfl_xor_sync(0xffffffffu, mlg, o));
        mlp = fmaxf(mlp, __shfl_xor_sync(0xffffffffu, mlp, o));
    }
    float se = 0.f, sl = 0.f;
    #pragma unroll
    for (int k = 0; k < 4; ++k) {
        if (lane + 32 * k < CC) {
            se += __expf(lq[k] - mlp);
            sl += __expf(lg[k] - mlg);
        }
    }
    #pragma unroll
    for (int o = 16; o; o >>= 1) {
        se += __shfl_xor_sync(0xffffffffu, se, o);
        sl += __shfl_xor_sync(0xffffffffu, sl, o);
    }
    float marg = mlp + __logf(se);
    float logev = fminf(marg + 80.992775903f, 10.f);
    float E = __expf(logev) / sl;

    float* o = out + (size_t)n * (CC + 1);
    #pragma unroll
    for (int k = 0; k < 4; ++k) {
        int cc = lane + 32 * k;
        if (cc < CC)
            o[cc] = __logf(fmaf(E, __expf(lg[k] - mlg), 1.f));
    }
    if (lane == 0)
        o[CC] = lprow[labels[n]];
}

extern "C" void kernel_launch(void* const* d_in, const int* in_sizes, int n_in,
                              void* d_out, int out_size) {
    const float* x      = (const float*)d_in[0];
    const int*   labels = (const int*)d_in[1];
    const float* freq   = (const float*)d_in[2];
    const float* z0     = (const float*)d_in[3];
    const float* ap     = (const float*)d_in[4];
    const float* bp     = (const float*)d_in[5];
    const float* W      = (const float*)d_in[6];
    const float* b      = (const float*)d_in[7];
    float* out = (float*)d_out;

    cudaFuncSetAttribute(flow_kernel, cudaFuncAttributeMaxDynamicSharedMemorySize, SMEM_BYTES);

    prep_kernel<<<CC, 512>>>(z0, ap, bp);
    flow_kernel<<<NBLK, 128, SMEM_BYTES>>>(x, z0);
    out_kernel<<<NN / 32, 1024>>>(x, labels, freq, W, b, out);
}

// round 16
// speedup vs baseline: 1.2079x; 1.2079x over previous
#include <cuda_runtime.h>
#include <math.h>
#include <stdint.h>

#define NN 8192
#define DD 64
#define CC 100
#define TT 30
#define HC 50
#define NPAIR 465

// ---- device-global scratch ----
__device__ float g_lp[NN * CC];
__device__ float g_lg[NN * CC];        // raw logits (x . W[:,c]) from flow MMA
__device__ float g_G[CC * TT * 32];
__device__ float g_al[CC * 32];
__device__ float g_be[CC * 32];
__device__ float g_n0[CC * 32];

typedef unsigned long long u64;

__device__ __forceinline__ float2 upk2(u64 v) {
    float2 f; asm("mov.b64 {%0, %1}, %2;" : "=f"(f.x), "=f"(f.y) : "l"(v)); return f;
}
__device__ __forceinline__ u64 pk2(float lo, float hi) {
    u64 r; asm("mov.b64 %0, {%1, %2};" : "=l"(r) : "f"(lo), "f"(hi)); return r;
}
__device__ __forceinline__ u64 fma2(u64 a, u64 b, u64 c) {
    u64 d; asm("fma.rn.f32x2 %0, %1, %2, %3;" : "=l"(d) : "l"(a), "l"(b), "l"(c)); return d;
}
__device__ __forceinline__ u64 add2(u64 a, u64 b) {
    u64 d; asm("add.rn.f32x2 %0, %1, %2;" : "=l"(d) : "l"(a), "l"(b)); return d;
}
__device__ __forceinline__ int goff(int t) { return (t * (t - 1)) / 2 + (t >> 1); }

// ---- prep: per-class params + Gram (proven) ----
__global__ void __launch_bounds__(512) prep_kernel(const float* __restrict__ z0,
                                                   const float* __restrict__ ap,
                                                   const float* __restrict__ bp) {
    __shared__ float sz[TT * 65];
    const int tid = threadIdx.x;
    const int c = blockIdx.x;

    for (int i = tid; i < TT * DD; i += 512) {
        int r = i >> 6, col = i & 63;
        sz[r * 65 + col] = z0[(size_t)c * TT * DD + i];
    }
    if (tid < TT) {
        float a  = log1pf(__expf(ap[c * TT + tid]));
        float be = log1pf(__expf(bp[c * TT + tid])) - a;
        g_al[c * 32 + tid] = a;
        g_be[c * 32 + tid] = be;
    }
    __syncthreads();

    int k = tid;
    if (k < NPAIR) {
        int t = (int)((__fsqrt_rn(8.f * k + 1.f) - 1.f) * 0.5f);
        while ((t + 1) * (t + 2) / 2 <= k) ++t;
        while (t * (t + 1) / 2 > k) --t;
        int i = k - t * (t + 1) / 2;
        const float* za = sz + t * 65;
        const float* zb = sz + i * 65;
        float a0 = 0.f, a1 = 0.f, a2 = 0.f, a3 = 0.f;
        #pragma unroll
        for (int d = 0; d < DD; d += 4) {
            a0 = fmaf(za[d],     zb[d],     a0);
            a1 = fmaf(za[d + 1], zb[d + 1], a1);
            a2 = fmaf(za[d + 2], zb[d + 2], a2);
            a3 = fmaf(za[d + 3], zb[d + 3], a3);
        }
        float dot = (a0 + a1) + (a2 + a3);
        if (i == t) g_n0[c * 32 + t] = dot;
        else        g_G[(size_t)c * TT * 32 + t * 32 + i] = dot;
    }
}

__device__ __forceinline__ void mma_tf32(float& c0, float& c1, float& c2, float& c3,
                                         uint32_t a0, uint32_t a1, uint32_t a2, uint32_t a3,
                                         uint32_t b0, uint32_t b1) {
    asm volatile(
        "mma.sync.aligned.m16n8k8.row.col.f32.tf32.tf32.f32 "
        "{%0,%1,%2,%3}, {%4,%5,%6,%7}, {%8,%9}, {%0,%1,%2,%3};"
        : "+f"(c0), "+f"(c1), "+f"(c2), "+f"(c3)
        : "r"(a0), "r"(a1), "r"(a2), "r"(a3), "r"(b0), "r"(b1));
}

// dynamic smem (float indices):
//  sx  [0, 8704)        x tile 128 x 68; aliased by spq (u64 128 x 33)
//  szz [8704, 13056)    two z0 tiles (32 x 68 each); row 30 = W column, row 31 = 0
//  sGc [13056, 13956)   compact paired Gram (u64[450])
//  prm [13956, 14148)
#define OFF_Z   8704
#define OFF_GC  13056
#define OFF_PRM 13956
#define SMEM_FLOATS 14148
#define SMEM_BYTES (SMEM_FLOATS * 4)   // 56592 B -> 4 blocks/SM

// ---- flow: block = 128 samples x 2 classes; MMA also yields logits (row 30) ----
__global__ void __launch_bounds__(128, 4) flow_kernel(const float* __restrict__ x,
                                                      const float* __restrict__ z0g,
                                                      const float* __restrict__ W) {
    extern __shared__ __align__(16) float sm[];
    float* sx   = sm;
    float* szz  = sm + OFF_Z;
    u64*   sGc  = (u64*)(sm + OFF_GC);
    float* prmA = sm + OFF_PRM;
    float* prmB = sm + OFF_PRM + 96;

    const int tid = threadIdx.x;
    const int wid = tid >> 5;
    const int lane = tid & 31;
    const int g = lane >> 2;
    const int cc4 = lane & 3;
    const int c0 = blockIdx.y;
    const int c1 = c0 + HC;
    const int nbase = blockIdx.x * 128;

    // stage x tile (pitch 17 float4)
    {
        const float4* gx = (const float4*)(x + (size_t)nbase * DD);
        float4* s4 = (float4*)sx;
        #pragma unroll
        for (int j = 0; j < 16; ++j) {
            int idx = tid + 128 * j;
            int r = idx >> 4, col = idx & 15;
            s4[r * 17 + col] = gx[idx];
        }
    }
    // stage both z0 tiles: rows 0..29 = z0, row 30 = W column, row 31 = 0
    {
        const float* gz0 = z0g + (size_t)c0 * TT * DD;
        const float* gz1 = z0g + (size_t)c1 * TT * DD;
        #pragma unroll
        for (int i = tid; i < 3840; i += 128) {    // rows 0..29 only
            int cls = (i >= 1920);
            int ii = i - cls * 1920;
            int r = ii >> 6, col = ii & 63;
            const float* gz = cls ? gz1 : gz0;
            szz[cls * 2176 + r * 68 + col] = gz[ii];
        }
        // rows 30 (W) and 31 (zero): 128 threads = 2 tiles x 64 dims
        int cls = tid >> 6, d = tid & 63;
        szz[cls * 2176 + 30 * 68 + d] = W[d * CC + (cls ? c1 : c0)];
        szz[cls * 2176 + 31 * 68 + d] = 0.f;
    }
    // compact paired Gram from prep output
    {
        const float* GA = g_G + (size_t)c0 * TT * 32;
        const float* GB = g_G + (size_t)c1 * TT * 32;
        for (int k = tid; k < 450; k += 128) {
            int t = (int)__fsqrt_rn(2.f * k);
            if (t < 1) t = 1;
            if (t > 29) t = 29;
            while (t < 29 && goff(t + 1) <= k) ++t;
            while (goff(t) > k) --t;
            int i = k - goff(t);
            float a = (i < t) ? GA[t * 32 + i] : 0.f;
            float b = (i < t) ? GB[t * 32 + i] : 0.f;
            sGc[k] = pk2(a, b);
        }
    }
    // params
    if (tid < 64) {
        int cls = tid >> 5, t = tid & 31;
        int c = cls ? c1 : c0;
        float* p = cls ? prmB : prmA;
        p[t]      = g_al[c * 32 + t];
        p[32 + t] = g_be[c * 32 + t];
        p[64 + t] = g_n0[c * 32 + t];
    }
    __syncthreads();

    // q0 = ||x||^2 (own row)
    float q0;
    {
        const float4* xr = ((const float4*)sx) + tid * 17;
        float a0 = 0.f, a1 = 0.f, a2 = 0.f, a3 = 0.f;
        #pragma unroll
        for (int j = 0; j < 16; ++j) {
            float4 v = xr[j];
            a0 = fmaf(v.x, v.x, a0);
            a1 = fmaf(v.y, v.y, a1);
            a2 = fmaf(v.z, v.z, a2);
            a3 = fmaf(v.w, v.w, a3);
        }
        q0 = (a0 + a1) + (a2 + a3);
    }

    // ---- MMA: P[32 samples x 32 cols] per warp, both classes (col 30 = logit) ----
    float CA[2][4][4], CB[2][4][4];
    #pragma unroll
    for (int mt = 0; mt < 2; ++mt)
        #pragma unroll
        for (int nt = 0; nt < 4; ++nt)
            #pragma unroll
            for (int r = 0; r < 4; ++r) { CA[mt][nt][r] = 0.f; CB[mt][nt][r] = 0.f; }

    const uint32_t* xa  = (const uint32_t*)(sx + (32 * wid + g) * 68);
    const uint32_t* zbA = (const uint32_t*)(szz + g * 68);
    const uint32_t* zbB = (const uint32_t*)(szz + 2176 + g * 68);

    #pragma unroll
    for (int ks = 0; ks < 8; ++ks) {
        int k0 = 8 * ks + cc4;
        uint32_t a00 = xa[k0],               a01 = xa[8 * 68 + k0];
        uint32_t a02 = xa[k0 + 4],           a03 = xa[8 * 68 + k0 + 4];
        uint32_t a10 = xa[16 * 68 + k0],     a11 = xa[24 * 68 + k0];
        uint32_t a12 = xa[16 * 68 + k0 + 4], a13 = xa[24 * 68 + k0 + 4];
        #pragma unroll
        for (int nt = 0; nt < 4; ++nt) {
            uint32_t bA0 = zbA[nt * 8 * 68 + k0];
            uint32_t bA1 = zbA[nt * 8 * 68 + k0 + 4];
            mma_tf32(CA[0][nt][0], CA[0][nt][1], CA[0][nt][2], CA[0][nt][3],
                     a00, a01, a02, a03, bA0, bA1);
            mma_tf32(CA[1][nt][0], CA[1][nt][1], CA[1][nt][2], CA[1][nt][3],
                     a10, a11, a12, a13, bA0, bA1);
            uint32_t bB0 = zbB[nt * 8 * 68 + k0];
            uint32_t bB1 = zbB[nt * 8 * 68 + k0 + 4];
            mma_tf32(CB[0][nt][0], CB[0][nt][1], CB[0][nt][2], CB[0][nt][3],
                     a00, a01, a02, a03, bB0, bB1);
            mma_tf32(CB[1][nt][0], CB[1][nt][1], CB[1][nt][2], CB[1][nt][3],
                     a10, a11, a12, a13, bB0, bB1);
        }
    }
    __syncthreads();   // x tile reads done -> alias sp

    // write paired P: spq[s*33 + t] = {pA, pB}
    u64* spq = (u64*)sx;
    #pragma unroll
    for (int mt = 0; mt < 2; ++mt) {
        #pragma unroll
        for (int nt = 0; nt < 4; ++nt) {
            int s0 = 32 * wid + mt * 16 + g;
            int t0 = nt * 8 + 2 * cc4;
            spq[s0 * 33 + t0]           = pk2(CA[mt][nt][0], CB[mt][nt][0]);
            spq[s0 * 33 + t0 + 1]       = pk2(CA[mt][nt][1], CB[mt][nt][1]);
            spq[(s0 + 8) * 33 + t0]     = pk2(CA[mt][nt][2], CB[mt][nt][2]);
            spq[(s0 + 8) * 33 + t0 + 1] = pk2(CA[mt][nt][3], CB[mt][nt][3]);
        }
    }
    __syncwarp();

    // logits out (col 30)
    {
        float2 lg2 = upk2(spq[tid * 33 + 30]);
        g_lg[(size_t)(nbase + tid) * CC + c0] = lg2.x;
        g_lg[(size_t)(nbase + tid) * CC + c1] = lg2.y;
    }

    // ---- packed dual-class chain (compact Gram rows) ----
    u64 wp[TT];
    float qA = q0, qB = q0;
    float gA = 1.f, gB = 1.f, giA = 1.f, giB = 1.f, prodA = 1.f, prodB = 1.f;

    #pragma unroll
    for (int t = 0; t < TT; ++t) {
        const u64* G2 = sGc + goff(t);
        u64 acc0 = 0ull, acc1 = 0ull;
        int i = 0;
        #pragma unroll
        for (; i + 2 <= t; i += 2) {
            ulonglong2 gq = *(const ulonglong2*)(G2 + i);
            acc0 = fma2(wp[i],     gq.x, acc0);
            acc1 = fma2(wp[i + 1], gq.y, acc1);
        }
        if (i < t) acc0 = fma2(wp[i], G2[i], acc0);
        float2 dot = upk2(add2(add2(acc0, acc1), spq[tid * 33 + t]));

        float sA = gA * dot.x;
        float sB = gB * dot.y;

        float alA = prmA[t], beA = prmA[32 + t], nnA = prmA[64 + t];
        float alB = prmB[t], beB = prmB[32 + t], nnB = prmB[64 + t];

        float r2A = fmaxf(fmaf(-2.f, sA, qA) + nnA, 1e-20f);
        float r2B = fmaxf(fmaf(-2.f, sB, qB) + nnB, 1e-20f);
        float rinA = rsqrtf(r2A), rinB = rsqrtf(r2B);
        float rA = r2A * rinA,    rB = r2B * rinB;
        float dA = alA + rA,      dB = alB + rB;
        float hA = __frcp_rn(dA),        hB = __frcp_rn(dB);
        float vA = __frcp_rn(dA + beA),  vB = __frcp_rn(dB + beB);
        float bhA = beA * hA,     bhB = beB * hB;
        float opA = 1.f + bhA,    opB = 1.f + bhB;
        float t2A = opA - bhA * (hA * rA);
        float t2B = opB - bhB * (hB * rB);
        prodA *= t2A;             prodB *= t2B;
        qA = fmaf(bhA * bhA, r2A, fmaf(2.f * bhA, qA - sA, qA));
        qB = fmaf(bhB * bhB, r2B, fmaf(2.f * bhB, qB - sB, qB));
        gA *= opA;                gB *= opB;
        giA *= dA * vA;           giB *= dB * vB;
        wp[t] = pk2(-bhA * giA, -bhB * giB);
    }

    float lpA = 63.f * __logf(gA) + __logf(prodA) - 0.5f * qA - 58.8120661251f;
    float lpB = 63.f * __logf(gB) + __logf(prodB) - 0.5f * qB - 58.8120661251f;
    g_lp[(size_t)(nbase + tid) * CC + c0] = lpA;
    g_lp[(size_t)(nbase + tid) * CC + c1] = lpB;
}

// ---- epilogue: warp = sample; logits precomputed -> pure softmax/posterior ----
__global__ void __launch_bounds__(1024, 1) out_kernel(const int* __restrict__ labels,
                                                      const float* __restrict__ freq,
                                                      const float* __restrict__ b,
                                                      float* __restrict__ out) {
    __shared__ float sb[CC], slf[CC];
    const int tid = threadIdx.x;
    for (int i = tid; i < CC; i += 1024) { sb[i] = b[i]; slf[i] = __logf(freq[i]); }
    __syncthreads();

    const int wid = tid >> 5, lane = tid & 31;
    const int n = blockIdx.x * 32 + wid;

    const float* lprow = g_lp + (size_t)n * CC;
    const float* lgrow = g_lg + (size_t)n * CC;
    float lg[4], lq[4];
    float mlg = -1e30f, mlp = -1e30f;
    #pragma unroll
    for (int k = 0; k < 4; ++k) {
        int cc = lane + 32 * k;
        if (cc < CC) {
            lg[k] = lgrow[cc] + sb[cc];
            lq[k] = lprow[cc] + slf[cc];
        } else {
            lg[k] = -1e30f; lq[k] = -1e30f;
        }
        mlg = fmaxf(mlg, lg[k]);
        mlp = fmaxf(mlp, lq[k]);
    }
    #pragma unroll
    for (int o = 16; o; o >>= 1) {
        mlg = fmaxf(mlg, __shfl_xor_sync(0xffffffffu, mlg, o));
        mlp = fmaxf(mlp, __shfl_xor_sync(0xffffffffu, mlp, o));
    }
    float se = 0.f, sl = 0.f;
    #pragma unroll
    for (int k = 0; k < 4; ++k) {
        if (lane + 32 * k < CC) {
            se += __expf(lq[k] - mlp);
            sl += __expf(lg[k] - mlg);
        }
    }
    #pragma unroll
    for (int o = 16; o; o >>= 1) {
        se += __shfl_xor_sync(0xffffffffu, se, o);
        sl += __shfl_xor_sync(0xffffffffu, sl, o);
    }
    float marg = mlp + __logf(se);
    float logev = fminf(marg + 80.992775903f, 10.f);
    float E = __expf(logev) / sl;

    float* o = out + (size_t)n * (CC + 1);
    #pragma unroll
    for (int k = 0; k < 4; ++k) {
        int cc = lane + 32 * k;
        if (cc < CC)
            o[cc] = __logf(fmaf(E, __expf(lg[k] - mlg), 1.f));
    }
    if (lane == 0)
        o[CC] = lprow[labels[n]];
}

extern "C" void kernel_launch(void* const* d_in, const int* in_sizes, int n_in,
                              void* d_out, int out_size) {
    const float* x      = (const float*)d_in[0];
    const int*   labels = (const int*)d_in[1];
    const float* freq   = (const float*)d_in[2];
    const float* z0     = (const float*)d_in[3];
    const float* ap     = (const float*)d_in[4];
    const float* bp     = (const float*)d_in[5];
    const float* W      = (const float*)d_in[6];
    const float* b      = (const float*)d_in[7];
    float* out = (float*)d_out;

    cudaFuncSetAttribute(flow_kernel, cudaFuncAttributeMaxDynamicSharedMemorySize, SMEM_BYTES);

    prep_kernel<<<CC, 512>>>(z0, ap, bp);
    dim3 grid(NN / 128, HC);
    flow_kernel<<<grid, 128, SMEM_BYTES>>>(x, z0, W);
    out_kernel<<<NN / 32, 1024>>>(labels, freq, b, out);
}